// round 15
// baseline (speedup 1.0000x reference)
#include <cuda_runtime.h>
#include <cuda_bf16.h>
#include <cstdint>

// ---------------------------------------------------------------------------
// FCOS decoder heads. Conv3x3 on tensor cores (mma.sync.m16n8k16.bf16),
// 3-term hi/lo bf16 split: W*X ~= Wh*Xh + Wl*Xh + Wh*Xl.
// 512 threads / 16 warps; tile 64 oc x 24x16 px; double-buffered smem with
// cp.async weight fills and register-staged halo prefetch (2-stage pipeline).
// Heads merged in one launch (grid.z = 2 heads x 4 batch).
// Output order: cls0..4, reg0..4, ctr0..4.
// ---------------------------------------------------------------------------

#define ICH 256
#define OCH 256
#define NB  4

#define TY 24
#define TX 16
#define HY 26
#define HX 18
#define HPX (HY * HX)          // 468
#define HWORDS (HPX * 8)       // 3744 halo (px, ic-pair) elements per chunk
#define SW_W (2 * 9 * 64 * 12) // 13824 words per weight buffer
#define SXH (HPX * 12)         // 5616 words, hi/lo stride inside halo buffer
#define SX_W (2 * SXH)         // 11232 words per halo buffer
#define SMEM_WORDS (2 * (SW_W + SX_W))   // 50112
#define SMEM_BYTES (SMEM_WORDS * 4)      // 200448

// Scratch (no cudaMalloc allowed). Buffers hold both heads: [head][n][c][hw].
__device__ float g_bufA[(size_t)2 * NB * ICH * 128 * 128];   // 128 MiB
__device__ float g_bufB[(size_t)2 * NB * ICH * 128 * 128];   // 128 MiB
// packed bf16-pair words: [head][layer][chunk16][h(hi/lo)][tap9][oc256][w8]
__device__ uint32_t g_wb[(size_t)2 * 4 * 16 * 2 * 9 * 256 * 8];
__device__ float g_wfc[80 * 256];                            // cls final, [ic][oc]

// ---- helpers ---------------------------------------------------------------
__device__ __forceinline__ uint32_t packbf(__nv_bfloat16 a, __nv_bfloat16 b) {
    __nv_bfloat162 t(a, b);
    return *reinterpret_cast<uint32_t*>(&t);
}

__device__ __forceinline__ void mma16816(float* d, const uint32_t* a,
                                         const uint32_t* b) {
    asm volatile(
        "mma.sync.aligned.m16n8k16.row.col.f32.bf16.bf16.f32 "
        "{%0,%1,%2,%3},{%4,%5,%6,%7},{%8,%9},{%0,%1,%2,%3};"
        : "+f"(d[0]), "+f"(d[1]), "+f"(d[2]), "+f"(d[3])
        : "r"(a[0]), "r"(a[1]), "r"(a[2]), "r"(a[3]), "r"(b[0]), "r"(b[1]));
}

__device__ __forceinline__ void ldsm4(uint32_t* r, uint32_t saddr) {
    asm volatile(
        "ldmatrix.sync.aligned.m8n8.x4.shared.b16 {%0,%1,%2,%3}, [%4];"
        : "=r"(r[0]), "=r"(r[1]), "=r"(r[2]), "=r"(r[3]) : "r"(saddr));
}

__device__ __forceinline__ void cpasync16(uint32_t sdst, const void* gsrc) {
    asm volatile("cp.async.cg.shared.global [%0], [%1], 16;"
                 :: "r"(sdst), "l"(gsrc));
}

// ---------------------------------------------------------------------------
// Weight split/pack: fp32 (4, OC, IC, 3, 3) ->
//   words [(layer,chunk,h,tap,oc,w)] ; word = bf16(ic=2w) | bf16(ic=2w+1)<<16
// ---------------------------------------------------------------------------
__global__ void wsplit(const float* __restrict__ w, uint32_t* __restrict__ out) {
    long i = (long)blockIdx.x * blockDim.x + threadIdx.x;
    const long total = 4L * 16 * 2 * 9 * 256 * 8;
    if (i >= total) return;
    int wd = (int)(i & 7);
    long t = i >> 3;
    int oc = (int)(t & 255); t >>= 8;
    int tap = (int)(t % 9); t /= 9;
    int h = (int)(t & 1); t >>= 1;
    int chunk = (int)(t & 15); t >>= 4;
    int layer = (int)t;
    int ic0 = chunk * 16 + wd * 2;
    float v0 = w[(((long)(layer * 256 + oc) * 256 + ic0) * 9) + tap];
    float v1 = w[(((long)(layer * 256 + oc) * 256 + ic0 + 1) * 9) + tap];
    __nv_bfloat16 h0 = __float2bfloat16_rn(v0);
    __nv_bfloat16 h1 = __float2bfloat16_rn(v1);
    if (h == 0) {
        out[i] = packbf(h0, h1);
    } else {
        __nv_bfloat16 l0 = __float2bfloat16_rn(v0 - __bfloat162float(h0));
        __nv_bfloat16 l1 = __float2bfloat16_rn(v1 - __bfloat162float(h1));
        out[i] = packbf(l0, l1);
    }
}

// cls final weights: (80, 256) -> (256, 80)
__global__ void transpose_fc(const float* __restrict__ w,
                             float* __restrict__ wT) {
    int i = blockIdx.x * blockDim.x + threadIdx.x;
    if (i >= 80 * 256) return;
    int oc = i % 80;
    int ic = i / 80;
    wT[i] = w[oc * 256 + ic];
}

// ---------------------------------------------------------------------------
// conv3x3 + BN + ReLU, pipelined tensor-core kernel.
// smem: sW[buf] at buf*SW_W words, sX[buf] at 2*SW_W + buf*SX_W words.
// sW row: [h2][tap9][oc64][12w]; sX: [h2][px468][12w] (px = y*18 + x).
// ---------------------------------------------------------------------------
__global__ __launch_bounds__(512, 1)
void conv3x3_mma(const float* __restrict__ src0,   // head 0 input (n-major)
                 const float* __restrict__ src1,   // head 1 input
                 const uint32_t* __restrict__ wb0, // head 0 layer weights
                 const uint32_t* __restrict__ wb1, // head 1 layer weights
                 const float* __restrict__ sc0, const float* __restrict__ sc1,
                 const float* __restrict__ bi0, const float* __restrict__ bi1,
                 float* __restrict__ dstbase,      // + head*headStride
                 size_t headStride,
                 int H, int W) {
    extern __shared__ uint32_t sm[];
    const uint32_t smB = (uint32_t)__cvta_generic_to_shared(sm);

    const int tid = threadIdx.x;
    const int lane = tid & 31;
    const int wid = tid >> 5;
    const int warp_m = wid & 1;
    const int warp_n = wid >> 1;           // 0..7 (3 output rows each)
    const int lq = lane >> 2;              // 0..7
    const int lr = lane & 3;               // 0..3

    const int tilesX = (W + TX - 1) / TX;
    const int tileX = blockIdx.x % tilesX;
    const int tileY = blockIdx.x / tilesX;
    const int ocb = blockIdx.y << 6;
    const int z = blockIdx.z;
    const int n = z & 3;
    const int head = z >> 2;
    const int gx0 = tileX * TX;
    const int gy0 = tileY * TY;
    const int HW = H * W;

    const float* inN = (head ? src1 : src0) + (size_t)n * ICH * HW;
    const uint32_t* wb = head ? wb1 : wb0;

    // ldmatrix per-thread byte offsets (identical to verified round-13 maps)
    const uint32_t aoff = ((lane & 15) * 12 + (lane >> 4) * 4) * 4;
    const uint32_t boff = (((lane >> 4) * 8 + (lane & 7)) * 12 +
                           ((lane >> 3) & 1) * 4) * 4;

    // incremental halo indexing: element i = tid + 512k -> (px, wd)
    const int px0 = tid % HPX;
    const int wd0 = tid / HPX;
    const int lastk_lim = HWORDS - 7 * 512;   // 160

    float acc[2][6][4];
#pragma unroll
    for (int mi = 0; mi < 2; ++mi)
#pragma unroll
        for (int ni = 0; ni < 6; ++ni)
#pragma unroll
            for (int k = 0; k < 4; ++k) acc[mi][ni][k] = 0.f;

    float hv0[8], hv1[8];

    // ================= prologue: fill chunk 0 into buffer 0 =================
    {
        int px = px0, wd = wd0;
#pragma unroll
        for (int k = 0; k < 8; ++k) {
            hv0[k] = 0.f; hv1[k] = 0.f;
            if (k < 7 || tid < lastk_lim) {
                int y = px / HX, x = px % HX;
                int gy = gy0 + y - 1, gx = gx0 + x - 1;
                if ((unsigned)gy < (unsigned)H && (unsigned)gx < (unsigned)W) {
                    const float* p = inN + (size_t)(2 * wd) * HW + gy * W + gx;
                    hv0[k] = p[0];
                    hv1[k] = p[HW];
                }
            }
            px += 44; ++wd; if (px >= HPX) { px -= HPX; ++wd; }
        }
        // weights chunk 0 -> buffer 0
        const uint32_t* wsrc = wb;
        for (int i = tid; i < 2304; i += 512) {
            int wd4 = (i & 1) * 4;
            int t = i >> 1;
            int oc = t & 63; t >>= 6;
            int tap = t % 9, h = t / 9;
            cpasync16(smB + ((((h * 9 + tap) * 64 + oc) * 12 + wd4) << 2),
                      wsrc + ((size_t)((h * 9 + tap) * 256) + ocb + oc) * 8 + wd4);
        }
        asm volatile("cp.async.commit_group;");
        // halo STS chunk 0 -> buffer 0
        uint32_t* sXn = sm + 2 * SW_W;
        px = px0; wd = wd0;
#pragma unroll
        for (int k = 0; k < 8; ++k) {
            if (k < 7 || tid < lastk_lim) {
                __nv_bfloat16 h0 = __float2bfloat16_rn(hv0[k]);
                __nv_bfloat16 h1 = __float2bfloat16_rn(hv1[k]);
                __nv_bfloat16 l0 = __float2bfloat16_rn(hv0[k] - __bfloat162float(h0));
                __nv_bfloat16 l1 = __float2bfloat16_rn(hv1[k] - __bfloat162float(h1));
                sXn[px * 12 + wd] = packbf(h0, h1);
                sXn[SXH + px * 12 + wd] = packbf(l0, l1);
            }
            px += 44; ++wd; if (px >= HPX) { px -= HPX; ++wd; }
        }
        asm volatile("cp.async.wait_group 0;" ::: "memory");
        __syncthreads();
    }

    // ============================ main loop ================================
    for (int c = 0; c < 16; ++c) {
        const int buf = c & 1;
        const uint32_t sWb = smB + (buf * SW_W) * 4;
        const uint32_t sXb = smB + (2 * SW_W + buf * SX_W) * 4;

        if (c < 15) {
            // prefetch chunk c+1 halo into registers (latency overlaps taps)
            const int ic0n = (c + 1) << 4;
            int px = px0, wd = wd0;
#pragma unroll
            for (int k = 0; k < 8; ++k) {
                hv0[k] = 0.f; hv1[k] = 0.f;
                if (k < 7 || tid < lastk_lim) {
                    int y = px / HX, x = px % HX;
                    int gy = gy0 + y - 1, gx = gx0 + x - 1;
                    if ((unsigned)gy < (unsigned)H && (unsigned)gx < (unsigned)W) {
                        const float* p = inN + (size_t)(ic0n + 2 * wd) * HW + gy * W + gx;
                        hv0[k] = p[0];
                        hv1[k] = p[HW];
                    }
                }
                px += 44; ++wd; if (px >= HPX) { px -= HPX; ++wd; }
            }
            // weights chunk c+1 -> other buffer via cp.async
            const uint32_t* wsrc = wb + (size_t)(c + 1) * (2 * 9 * 256 * 8);
            const uint32_t dstb = smB + ((buf ^ 1) * SW_W) * 4;
            for (int i = tid; i < 2304; i += 512) {
                int wd4 = (i & 1) * 4;
                int t = i >> 1;
                int oc = t & 63; t >>= 6;
                int tap = t % 9, h = t / 9;
                cpasync16(dstb + ((((h * 9 + tap) * 64 + oc) * 12 + wd4) << 2),
                          wsrc + ((size_t)((h * 9 + tap) * 256) + ocb + oc) * 8 + wd4);
            }
            asm volatile("cp.async.commit_group;");
        }

        // ---- compute 9 taps from current buffers ----
        int dy = 0, dx = 0;
        for (int tap = 0; tap < 9; ++tap) {
            uint32_t ah[2][4], al[2][4];
#pragma unroll
            for (int mi = 0; mi < 2; ++mi) {
                uint32_t a0 = sWb +
                    (((tap * 64 + warp_m * 32 + mi * 16) * 12) << 2) + aoff;
                ldsm4(ah[mi], a0);
                ldsm4(al[mi], a0 + (6912 << 2));
            }
#pragma unroll
            for (int p = 0; p < 3; ++p) {
                uint32_t b0 = sXb +
                    ((((warp_n * 3 + p + dy) * HX + dx) * 12) << 2) + boff;
                uint32_t bh[4], bl[4];
                ldsm4(bh, b0);
                ldsm4(bl, b0 + (SXH << 2));
#pragma unroll
                for (int mi = 0; mi < 2; ++mi) {
                    mma16816(acc[mi][2 * p],     ah[mi], bh);
                    mma16816(acc[mi][2 * p],     al[mi], bh);
                    mma16816(acc[mi][2 * p],     ah[mi], bl);
                    mma16816(acc[mi][2 * p + 1], ah[mi], bh + 2);
                    mma16816(acc[mi][2 * p + 1], al[mi], bh + 2);
                    mma16816(acc[mi][2 * p + 1], ah[mi], bl + 2);
                }
            }
            if (++dx == 3) { dx = 0; ++dy; }
        }

        if (c < 15) {
            // convert + store halo chunk c+1 into other buffer
            uint32_t* sXn = sm + (2 * SW_W + (buf ^ 1) * SX_W);
            int px = px0, wd = wd0;
#pragma unroll
            for (int k = 0; k < 8; ++k) {
                if (k < 7 || tid < lastk_lim) {
                    __nv_bfloat16 h0 = __float2bfloat16_rn(hv0[k]);
                    __nv_bfloat16 h1 = __float2bfloat16_rn(hv1[k]);
                    __nv_bfloat16 l0 = __float2bfloat16_rn(hv0[k] - __bfloat162float(h0));
                    __nv_bfloat16 l1 = __float2bfloat16_rn(hv1[k] - __bfloat162float(h1));
                    sXn[px * 12 + wd] = packbf(h0, h1);
                    sXn[SXH + px * 12 + wd] = packbf(l0, l1);
                }
                px += 44; ++wd; if (px >= HPX) { px -= HPX; ++wd; }
            }
        }
        asm volatile("cp.async.wait_group 0;" ::: "memory");
        __syncthreads();
    }

    // ---- epilogue: BN fold + ReLU ----
    const float* scale = head ? sc1 : sc0;
    const float* bias  = head ? bi1 : bi0;
    float* outN = dstbase + (size_t)head * headStride;
#pragma unroll
    for (int mi = 0; mi < 2; ++mi) {
        const int oc0 = ocb + warp_m * 32 + mi * 16 + lq;
        const int oc1 = oc0 + 8;
        const float s0 = scale[oc0], b0 = bias[oc0];
        const float s1 = scale[oc1], b1 = bias[oc1];
        float* o0 = outN + ((size_t)n * OCH + oc0) * HW;
        float* o1 = outN + ((size_t)n * OCH + oc1) * HW;
#pragma unroll
        for (int ni = 0; ni < 6; ++ni) {
            const int py = warp_n * 3 + (ni >> 1);
            const int pxx = (ni & 1) * 8 + lr * 2;
            if (gy0 + py < H && gx0 + pxx < W) {
                const size_t pix = (size_t)(gy0 + py) * W + gx0 + pxx;
                float2 v0, v1;
                v0.x = fmaxf(fmaf(acc[mi][ni][0], s0, b0), 0.f);
                v0.y = fmaxf(fmaf(acc[mi][ni][1], s0, b0), 0.f);
                v1.x = fmaxf(fmaf(acc[mi][ni][2], s1, b1), 0.f);
                v1.y = fmaxf(fmaf(acc[mi][ni][3], s1, b1), 0.f);
                *(float2*)(o0 + pix) = v0;
                *(float2*)(o1 + pix) = v1;
            }
        }
    }
}

// ---------------------------------------------------------------------------
// cls final: 1x1 conv 256 -> 80 (+bias). Block: 32 pixels, 8 groups x 10 oc.
// ---------------------------------------------------------------------------
__global__ __launch_bounds__(256)
void final_conv_cls(const float* __restrict__ in,
                    const float* __restrict__ wT,
                    const float* __restrict__ b,
                    float* __restrict__ out, int HW) {
    __shared__ float xs[8192];
    __shared__ float ws[32 * 80];

    const int tid = threadIdx.x;
    const long p0 = (long)blockIdx.x * 32;
    const int n = (int)(p0 / HW);
    const int s0 = (int)(p0 % HW);
    const float* inN = in + (size_t)n * 256 * HW + s0;

    for (int i = tid; i < 8192; i += 256) {
        int ic = i >> 5, p = i & 31;
        xs[i] = inN[(size_t)ic * HW + p];
    }

    const int px = tid & 31;
    const int g = tid >> 5;
    const int oc0 = g * 10;
    float acc[10];
#pragma unroll
    for (int j = 0; j < 10; ++j) acc[j] = b[oc0 + j];

    for (int ic0 = 0; ic0 < 256; ic0 += 32) {
        __syncthreads();
        for (int i = tid; i < 2560; i += 256) ws[i] = wT[ic0 * 80 + i];
        __syncthreads();
        for (int icc = 0; icc < 32; ++icc) {
            float x = xs[((ic0 + icc) << 5) + px];
            const float* wr = &ws[icc * 80 + oc0];
#pragma unroll
            for (int j = 0; j < 10; ++j) acc[j] = fmaf(x, wr[j], acc[j]);
        }
    }

    const int s = s0 + px;
#pragma unroll
    for (int j = 0; j < 10; ++j)
        out[((size_t)n * 80 + oc0 + j) * HW + s] = acc[j];
}

// ---------------------------------------------------------------------------
// reg final: 1x1 conv 256 -> 5 (+bias). ch0 -> centerness (raw),
// ch1..4 -> max(raw * stride, 0). w layout [oc(5)][ic(256)].
// ---------------------------------------------------------------------------
__global__ __launch_bounds__(256)
void final_conv_reg(const float* __restrict__ in,
                    const float* __restrict__ w,
                    const float* __restrict__ b,
                    float* __restrict__ out_reg,
                    float* __restrict__ out_ctr,
                    int HW, float stride) {
    __shared__ float xs[8192];
    __shared__ float ws[5 * 256];

    const int tid = threadIdx.x;
    for (int i = tid; i < 1280; i += 256) ws[i] = w[i];

    const long p0 = (long)blockIdx.x * 32;
    const int n = (int)(p0 / HW);
    const int s0 = (int)(p0 % HW);
    const float* inN = in + (size_t)n * 256 * HW + s0;
    for (int i = tid; i < 8192; i += 256) {
        int ic = i >> 5, p = i & 31;
        xs[i] = inN[(size_t)ic * HW + p];
    }
    __syncthreads();

    const int px = tid & 31;
    const int g = tid >> 5;
    if (g < 5) {
        float acc = b[g];
        const float* wr = &ws[g * 256];
        for (int ic = 0; ic < 256; ++ic)
            acc = fmaf(xs[(ic << 5) + px], wr[ic], acc);
        const int s = s0 + px;
        if (g == 0)
            out_ctr[(size_t)n * HW + s] = acc;
        else
            out_reg[((size_t)n * 4 + (g - 1)) * HW + s] = fmaxf(acc * stride, 0.f);
    }
}

// ---------------------------------------------------------------------------
// Host launcher
// ---------------------------------------------------------------------------
extern "C" void kernel_launch(void* const* d_in, const int* in_sizes, int n_in,
                              void* d_out, int out_size) {
    (void)in_sizes; (void)n_in; (void)out_size;

    const float* fpn[5];
    for (int i = 0; i < 5; ++i) fpn[i] = (const float*)d_in[i];
    const float* cls_conv_w  = (const float*)d_in[5];
    const float* cls_scale   = (const float*)d_in[6];
    const float* cls_bias    = (const float*)d_in[7];
    const float* cls_final_w = (const float*)d_in[8];
    const float* cls_final_b = (const float*)d_in[9];
    const float* reg_conv_w  = (const float*)d_in[10];
    const float* reg_scale   = (const float*)d_in[11];
    const float* reg_bias    = (const float*)d_in[12];
    const float* reg_final_w = (const float*)d_in[13];
    const float* reg_final_b = (const float*)d_in[14];
    float* out = (float*)d_out;

    float *bufA, *bufB, *wfc;
    uint32_t* wb;
    cudaGetSymbolAddress((void**)&bufA, g_bufA);
    cudaGetSymbolAddress((void**)&bufB, g_bufB);
    cudaGetSymbolAddress((void**)&wb,   g_wb);
    cudaGetSymbolAddress((void**)&wfc,  g_wfc);

    cudaFuncSetAttribute(conv3x3_mma,
                         cudaFuncAttributeMaxDynamicSharedMemorySize,
                         SMEM_BYTES);

    const long HEADWORDS = 4L * 16 * 2 * 9 * 256 * 8;   // per head
    const long LAYERWORDS = HEADWORDS / 4;
    const long wtot = HEADWORDS;

    wsplit<<<(int)((wtot + 255) / 256), 256>>>(cls_conv_w, wb);
    wsplit<<<(int)((wtot + 255) / 256), 256>>>(reg_conv_w, wb + HEADWORDS);
    transpose_fc<<<(80 * 256 + 255) / 256, 256>>>(cls_final_w, wfc);

    const int Hs[5] = {128, 64, 32, 16, 8};
    const float strides[5] = {8.f, 16.f, 32.f, 64.f, 128.f};
    long HWs[5], clsOff[5], regOff[5], ctrOff[5];
    for (int l = 0; l < 5; ++l) HWs[l] = (long)Hs[l] * Hs[l];
    long off = 0;
    for (int l = 0; l < 5; ++l) { clsOff[l] = off; off += (long)NB * 80 * HWs[l]; }
    for (int l = 0; l < 5; ++l) { regOff[l] = off; off += (long)NB * 4 * HWs[l]; }
    for (int l = 0; l < 5; ++l) { ctrOff[l] = off; off += (long)NB * 1 * HWs[l]; }

    for (int l = 0; l < 5; ++l) {
        const int H = Hs[l], W = Hs[l];
        const int HW = H * W;
        const size_t headStride = (size_t)NB * ICH * HW;
        const int tX = (W + TX - 1) / TX;
        const int tY = (H + TY - 1) / TY;
        dim3 grid(tX * tY, OCH / 64, NB * 2);

        // 4 merged conv layers (both heads per launch)
        const float* s0 = fpn[l];
        const float* s1 = fpn[l];
        float* dst = nullptr;
        for (int i = 0; i < 4; ++i) {
            dst = (i & 1) ? bufB : bufA;
            conv3x3_mma<<<grid, 512, SMEM_BYTES>>>(
                s0, s1,
                wb + 0 * HEADWORDS + i * LAYERWORDS,
                wb + 1 * HEADWORDS + i * LAYERWORDS,
                cls_scale + i * ICH, reg_scale + i * ICH,
                cls_bias + i * ICH,  reg_bias + i * ICH,
                dst, headStride, H, W);
            s0 = dst;                 // head 0 region
            s1 = dst + headStride;    // head 1 region
        }

        const int fgrid = NB * HW / 32;
        final_conv_cls<<<fgrid, 256>>>(s0, wfc, cls_final_b,
                                       out + clsOff[l], HW);
        final_conv_reg<<<fgrid, 256>>>(s1, reg_final_w, reg_final_b,
                                       out + regOff[l], out + ctrOff[l],
                                       HW, strides[l]);
    }
}

// round 16
// speedup vs baseline: 1.4947x; 1.4947x over previous
#include <cuda_runtime.h>
#include <cuda_bf16.h>
#include <cstdint>

// ---------------------------------------------------------------------------
// FCOS decoder heads. Conv3x3 on tensor cores (mma.sync.m16n8k16.bf16),
// 3-term hi/lo bf16 split: W*X ~= Wh*Xh + Wl*Xh + Wh*Xl.
// 512 threads / 16 warps; tile 64 oc x 24x16 px; double-buffered smem with
// cp.async weight fills and register-staged halo prefetch (2-stage pipeline).
// Heads merged in one launch (grid.z = 2 heads x 4 batch).
// Output order: cls0..4, reg0..4, ctr0..4.
// ---------------------------------------------------------------------------

#define ICH 256
#define OCH 256
#define NB  4

#define TY 24
#define TX 16
#define HY 26
#define HX 18
#define HPX (HY * HX)          // 468
#define HWORDS (HPX * 8)       // 3744 halo (px, ic-pair) elements per chunk
#define SW_W (2 * 9 * 64 * 12) // 13824 words per weight buffer
#define SXH (HPX * 12)         // 5616 words, hi/lo stride inside halo buffer
#define SX_W (2 * SXH)         // 11232 words per halo buffer
#define SMEM_WORDS (2 * (SW_W + SX_W))   // 50112
#define SMEM_BYTES (SMEM_WORDS * 4)      // 200448

// Scratch (no cudaMalloc allowed). Buffers hold both heads: [head][n][c][hw].
__device__ float g_bufA[(size_t)2 * NB * ICH * 128 * 128];   // 128 MiB
__device__ float g_bufB[(size_t)2 * NB * ICH * 128 * 128];   // 128 MiB
// packed bf16-pair words: [head][layer][chunk16][h(hi/lo)][tap9][oc256][w8]
__device__ uint32_t g_wb[(size_t)2 * 4 * 16 * 2 * 9 * 256 * 8];
__device__ float g_wfc[80 * 256];                            // cls final, [ic][oc]

// ---- helpers ---------------------------------------------------------------
__device__ __forceinline__ uint32_t packbf(__nv_bfloat16 a, __nv_bfloat16 b) {
    __nv_bfloat162 t(a, b);
    return *reinterpret_cast<uint32_t*>(&t);
}

__device__ __forceinline__ void mma16816(float* d, const uint32_t* a,
                                         const uint32_t* b) {
    asm volatile(
        "mma.sync.aligned.m16n8k16.row.col.f32.bf16.bf16.f32 "
        "{%0,%1,%2,%3},{%4,%5,%6,%7},{%8,%9},{%0,%1,%2,%3};"
        : "+f"(d[0]), "+f"(d[1]), "+f"(d[2]), "+f"(d[3])
        : "r"(a[0]), "r"(a[1]), "r"(a[2]), "r"(a[3]), "r"(b[0]), "r"(b[1]));
}

__device__ __forceinline__ void ldsm4(uint32_t* r, uint32_t saddr) {
    asm volatile(
        "ldmatrix.sync.aligned.m8n8.x4.shared.b16 {%0,%1,%2,%3}, [%4];"
        : "=r"(r[0]), "=r"(r[1]), "=r"(r[2]), "=r"(r[3]) : "r"(saddr));
}

__device__ __forceinline__ void cpasync16(uint32_t sdst, const void* gsrc) {
    asm volatile("cp.async.cg.shared.global [%0], [%1], 16;"
                 :: "r"(sdst), "l"(gsrc));
}

// ---------------------------------------------------------------------------
// Weight split/pack: fp32 (4, OC, IC, 3, 3) ->
//   words [(layer,chunk,h,tap,oc,w)] ; word = bf16(ic=2w) | bf16(ic=2w+1)<<16
// ---------------------------------------------------------------------------
__global__ void wsplit(const float* __restrict__ w, uint32_t* __restrict__ out) {
    long i = (long)blockIdx.x * blockDim.x + threadIdx.x;
    const long total = 4L * 16 * 2 * 9 * 256 * 8;
    if (i >= total) return;
    int wd = (int)(i & 7);
    long t = i >> 3;
    int oc = (int)(t & 255); t >>= 8;
    int tap = (int)(t % 9); t /= 9;
    int h = (int)(t & 1); t >>= 1;
    int chunk = (int)(t & 15); t >>= 4;
    int layer = (int)t;
    int ic0 = chunk * 16 + wd * 2;
    float v0 = w[(((long)(layer * 256 + oc) * 256 + ic0) * 9) + tap];
    float v1 = w[(((long)(layer * 256 + oc) * 256 + ic0 + 1) * 9) + tap];
    __nv_bfloat16 h0 = __float2bfloat16_rn(v0);
    __nv_bfloat16 h1 = __float2bfloat16_rn(v1);
    if (h == 0) {
        out[i] = packbf(h0, h1);
    } else {
        __nv_bfloat16 l0 = __float2bfloat16_rn(v0 - __bfloat162float(h0));
        __nv_bfloat16 l1 = __float2bfloat16_rn(v1 - __bfloat162float(h1));
        out[i] = packbf(l0, l1);
    }
}

// cls final weights: (80, 256) -> (256, 80)
__global__ void transpose_fc(const float* __restrict__ w,
                             float* __restrict__ wT) {
    int i = blockIdx.x * blockDim.x + threadIdx.x;
    if (i >= 80 * 256) return;
    int oc = i % 80;
    int ic = i / 80;
    wT[i] = w[oc * 256 + ic];
}

// ---------------------------------------------------------------------------
// conv3x3 + BN + ReLU, pipelined tensor-core kernel.
// smem: sW[buf] at buf*SW_W words, sX[buf] at 2*SW_W + buf*SX_W words.
// sW row: [h2][tap9][oc64][12w]; sX: [h2][px468][12w] (px = y*18 + x).
// ---------------------------------------------------------------------------
__global__ __launch_bounds__(512, 1)
void conv3x3_mma(const float* __restrict__ src0,   // head 0 input (n-major)
                 const float* __restrict__ src1,   // head 1 input
                 const uint32_t* __restrict__ wb0, // head 0 layer weights
                 const uint32_t* __restrict__ wb1, // head 1 layer weights
                 const float* __restrict__ sc0, const float* __restrict__ sc1,
                 const float* __restrict__ bi0, const float* __restrict__ bi1,
                 float* __restrict__ dstbase,      // + head*headStride
                 size_t headStride,
                 int H, int W) {
    extern __shared__ uint32_t sm[];
    const uint32_t smB = (uint32_t)__cvta_generic_to_shared(sm);

    const int tid = threadIdx.x;
    const int lane = tid & 31;
    const int wid = tid >> 5;
    const int warp_m = wid & 1;
    const int warp_n = wid >> 1;           // 0..7 (3 output rows each)
    const int lq = lane >> 2;              // 0..7
    const int lr = lane & 3;               // 0..3

    const int tilesX = (W + TX - 1) / TX;
    const int tileX = blockIdx.x % tilesX;
    const int tileY = blockIdx.x / tilesX;
    const int ocb = blockIdx.y << 6;
    const int z = blockIdx.z;
    const int n = z & 3;
    const int head = z >> 2;
    const int gx0 = tileX * TX;
    const int gy0 = tileY * TY;
    const int HW = H * W;

    const float* inN = (head ? src1 : src0) + (size_t)n * ICH * HW;
    const uint32_t* wb = head ? wb1 : wb0;

    // ldmatrix per-thread byte offsets (identical to verified round-13 maps)
    const uint32_t aoff = ((lane & 15) * 12 + (lane >> 4) * 4) * 4;
    const uint32_t boff = (((lane >> 4) * 8 + (lane & 7)) * 12 +
                           ((lane >> 3) & 1) * 4) * 4;

    // incremental halo indexing: element i = tid + 512k -> (px, wd)
    const int px0 = tid % HPX;
    const int wd0 = tid / HPX;
    const int lastk_lim = HWORDS - 7 * 512;   // 160

    float acc[2][6][4];
#pragma unroll
    for (int mi = 0; mi < 2; ++mi)
#pragma unroll
        for (int ni = 0; ni < 6; ++ni)
#pragma unroll
            for (int k = 0; k < 4; ++k) acc[mi][ni][k] = 0.f;

    float hv0[8], hv1[8];

    // ================= prologue: fill chunk 0 into buffer 0 =================
    {
        int px = px0, wd = wd0;
#pragma unroll
        for (int k = 0; k < 8; ++k) {
            hv0[k] = 0.f; hv1[k] = 0.f;
            if (k < 7 || tid < lastk_lim) {
                int y = px / HX, x = px % HX;
                int gy = gy0 + y - 1, gx = gx0 + x - 1;
                if ((unsigned)gy < (unsigned)H && (unsigned)gx < (unsigned)W) {
                    const float* p = inN + (size_t)(2 * wd) * HW + gy * W + gx;
                    hv0[k] = p[0];
                    hv1[k] = p[HW];
                }
            }
            px += 44; ++wd; if (px >= HPX) { px -= HPX; ++wd; }
        }
        // weights chunk 0 -> buffer 0
        const uint32_t* wsrc = wb;
        for (int i = tid; i < 2304; i += 512) {
            int wd4 = (i & 1) * 4;
            int t = i >> 1;
            int oc = t & 63; t >>= 6;
            int tap = t % 9, h = t / 9;
            cpasync16(smB + ((((h * 9 + tap) * 64 + oc) * 12 + wd4) << 2),
                      wsrc + ((size_t)((h * 9 + tap) * 256) + ocb + oc) * 8 + wd4);
        }
        asm volatile("cp.async.commit_group;");
        // halo STS chunk 0 -> buffer 0
        uint32_t* sXn = sm + 2 * SW_W;
        px = px0; wd = wd0;
#pragma unroll
        for (int k = 0; k < 8; ++k) {
            if (k < 7 || tid < lastk_lim) {
                __nv_bfloat16 h0 = __float2bfloat16_rn(hv0[k]);
                __nv_bfloat16 h1 = __float2bfloat16_rn(hv1[k]);
                __nv_bfloat16 l0 = __float2bfloat16_rn(hv0[k] - __bfloat162float(h0));
                __nv_bfloat16 l1 = __float2bfloat16_rn(hv1[k] - __bfloat162float(h1));
                sXn[px * 12 + wd] = packbf(h0, h1);
                sXn[SXH + px * 12 + wd] = packbf(l0, l1);
            }
            px += 44; ++wd; if (px >= HPX) { px -= HPX; ++wd; }
        }
        asm volatile("cp.async.wait_group 0;" ::: "memory");
        __syncthreads();
    }

    // ============================ main loop ================================
    for (int c = 0; c < 16; ++c) {
        const int buf = c & 1;
        const uint32_t sWb = smB + (buf * SW_W) * 4;
        const uint32_t sXb = smB + (2 * SW_W + buf * SX_W) * 4;

        if (c < 15) {
            // prefetch chunk c+1 halo into registers (latency overlaps taps)
            const int ic0n = (c + 1) << 4;
            int px = px0, wd = wd0;
#pragma unroll
            for (int k = 0; k < 8; ++k) {
                hv0[k] = 0.f; hv1[k] = 0.f;
                if (k < 7 || tid < lastk_lim) {
                    int y = px / HX, x = px % HX;
                    int gy = gy0 + y - 1, gx = gx0 + x - 1;
                    if ((unsigned)gy < (unsigned)H && (unsigned)gx < (unsigned)W) {
                        const float* p = inN + (size_t)(ic0n + 2 * wd) * HW + gy * W + gx;
                        hv0[k] = p[0];
                        hv1[k] = p[HW];
                    }
                }
                px += 44; ++wd; if (px >= HPX) { px -= HPX; ++wd; }
            }
            // weights chunk c+1 -> other buffer via cp.async
            const uint32_t* wsrc = wb + (size_t)(c + 1) * (2 * 9 * 256 * 8);
            const uint32_t dstb = smB + ((buf ^ 1) * SW_W) * 4;
            for (int i = tid; i < 2304; i += 512) {
                int wd4 = (i & 1) * 4;
                int t = i >> 1;
                int oc = t & 63; t >>= 6;
                int tap = t % 9, h = t / 9;
                cpasync16(dstb + ((((h * 9 + tap) * 64 + oc) * 12 + wd4) << 2),
                          wsrc + ((size_t)((h * 9 + tap) * 256) + ocb + oc) * 8 + wd4);
            }
            asm volatile("cp.async.commit_group;");
        }

        // ---- compute 9 taps from current buffers ----
        int dy = 0, dx = 0;
        for (int tap = 0; tap < 9; ++tap) {
            uint32_t ah[2][4], al[2][4];
#pragma unroll
            for (int mi = 0; mi < 2; ++mi) {
                uint32_t a0 = sWb +
                    (((tap * 64 + warp_m * 32 + mi * 16) * 12) << 2) + aoff;
                ldsm4(ah[mi], a0);
                ldsm4(al[mi], a0 + (6912 << 2));
            }
#pragma unroll
            for (int p = 0; p < 3; ++p) {
                uint32_t b0 = sXb +
                    ((((warp_n * 3 + p + dy) * HX + dx) * 12) << 2) + boff;
                uint32_t bh[4], bl[4];
                ldsm4(bh, b0);
                ldsm4(bl, b0 + (SXH << 2));
#pragma unroll
                for (int mi = 0; mi < 2; ++mi) {
                    mma16816(acc[mi][2 * p],     ah[mi], bh);
                    mma16816(acc[mi][2 * p],     al[mi], bh);
                    mma16816(acc[mi][2 * p],     ah[mi], bl);
                    mma16816(acc[mi][2 * p + 1], ah[mi], bh + 2);
                    mma16816(acc[mi][2 * p + 1], al[mi], bh + 2);
                    mma16816(acc[mi][2 * p + 1], ah[mi], bl + 2);
                }
            }
            if (++dx == 3) { dx = 0; ++dy; }
        }

        if (c < 15) {
            // convert + store halo chunk c+1 into other buffer
            uint32_t* sXn = sm + (2 * SW_W + (buf ^ 1) * SX_W);
            int px = px0, wd = wd0;
#pragma unroll
            for (int k = 0; k < 8; ++k) {
                if (k < 7 || tid < lastk_lim) {
                    __nv_bfloat16 h0 = __float2bfloat16_rn(hv0[k]);
                    __nv_bfloat16 h1 = __float2bfloat16_rn(hv1[k]);
                    __nv_bfloat16 l0 = __float2bfloat16_rn(hv0[k] - __bfloat162float(h0));
                    __nv_bfloat16 l1 = __float2bfloat16_rn(hv1[k] - __bfloat162float(h1));
                    sXn[px * 12 + wd] = packbf(h0, h1);
                    sXn[SXH + px * 12 + wd] = packbf(l0, l1);
                }
                px += 44; ++wd; if (px >= HPX) { px -= HPX; ++wd; }
            }
        }
        asm volatile("cp.async.wait_group 0;" ::: "memory");
        __syncthreads();
    }

    // ---- epilogue: BN fold + ReLU ----
    const float* scale = head ? sc1 : sc0;
    const float* bias  = head ? bi1 : bi0;
    float* outN = dstbase + (size_t)head * headStride;
#pragma unroll
    for (int mi = 0; mi < 2; ++mi) {
        const int oc0 = ocb + warp_m * 32 + mi * 16 + lq;
        const int oc1 = oc0 + 8;
        const float s0 = scale[oc0], b0 = bias[oc0];
        const float s1 = scale[oc1], b1 = bias[oc1];
        float* o0 = outN + ((size_t)n * OCH + oc0) * HW;
        float* o1 = outN + ((size_t)n * OCH + oc1) * HW;
#pragma unroll
        for (int ni = 0; ni < 6; ++ni) {
            const int py = warp_n * 3 + (ni >> 1);
            const int pxx = (ni & 1) * 8 + lr * 2;
            if (gy0 + py < H && gx0 + pxx < W) {
                const size_t pix = (size_t)(gy0 + py) * W + gx0 + pxx;
                float2 v0, v1;
                v0.x = fmaxf(fmaf(acc[mi][ni][0], s0, b0), 0.f);
                v0.y = fmaxf(fmaf(acc[mi][ni][1], s0, b0), 0.f);
                v1.x = fmaxf(fmaf(acc[mi][ni][2], s1, b1), 0.f);
                v1.y = fmaxf(fmaf(acc[mi][ni][3], s1, b1), 0.f);
                *(float2*)(o0 + pix) = v0;
                *(float2*)(o1 + pix) = v1;
            }
        }
    }
}

// ---------------------------------------------------------------------------
// cls final: 1x1 conv 256 -> 80 (+bias). Block: 32 pixels, 8 groups x 10 oc.
// ---------------------------------------------------------------------------
__global__ __launch_bounds__(256)
void final_conv_cls(const float* __restrict__ in,
                    const float* __restrict__ wT,
                    const float* __restrict__ b,
                    float* __restrict__ out, int HW) {
    __shared__ float xs[8192];
    __shared__ float ws[32 * 80];

    const int tid = threadIdx.x;
    const long p0 = (long)blockIdx.x * 32;
    const int n = (int)(p0 / HW);
    const int s0 = (int)(p0 % HW);
    const float* inN = in + (size_t)n * 256 * HW + s0;

    for (int i = tid; i < 8192; i += 256) {
        int ic = i >> 5, p = i & 31;
        xs[i] = inN[(size_t)ic * HW + p];
    }

    const int px = tid & 31;
    const int g = tid >> 5;
    const int oc0 = g * 10;
    float acc[10];
#pragma unroll
    for (int j = 0; j < 10; ++j) acc[j] = b[oc0 + j];

    for (int ic0 = 0; ic0 < 256; ic0 += 32) {
        __syncthreads();
        for (int i = tid; i < 2560; i += 256) ws[i] = wT[ic0 * 80 + i];
        __syncthreads();
        for (int icc = 0; icc < 32; ++icc) {
            float x = xs[((ic0 + icc) << 5) + px];
            const float* wr = &ws[icc * 80 + oc0];
#pragma unroll
            for (int j = 0; j < 10; ++j) acc[j] = fmaf(x, wr[j], acc[j]);
        }
    }

    const int s = s0 + px;
#pragma unroll
    for (int j = 0; j < 10; ++j)
        out[((size_t)n * 80 + oc0 + j) * HW + s] = acc[j];
}

// ---------------------------------------------------------------------------
// reg final: 1x1 conv 256 -> 5 (+bias). ch0 -> centerness (raw),
// ch1..4 -> max(raw * stride, 0). w layout [oc(5)][ic(256)].
// ---------------------------------------------------------------------------
__global__ __launch_bounds__(256)
void final_conv_reg(const float* __restrict__ in,
                    const float* __restrict__ w,
                    const float* __restrict__ b,
                    float* __restrict__ out_reg,
                    float* __restrict__ out_ctr,
                    int HW, float stride) {
    __shared__ float xs[8192];
    __shared__ float ws[5 * 256];

    const int tid = threadIdx.x;
    for (int i = tid; i < 1280; i += 256) ws[i] = w[i];

    const long p0 = (long)blockIdx.x * 32;
    const int n = (int)(p0 / HW);
    const int s0 = (int)(p0 % HW);
    const float* inN = in + (size_t)n * 256 * HW + s0;
    for (int i = tid; i < 8192; i += 256) {
        int ic = i >> 5, p = i & 31;
        xs[i] = inN[(size_t)ic * HW + p];
    }
    __syncthreads();

    const int px = tid & 31;
    const int g = tid >> 5;
    if (g < 5) {
        float acc = b[g];
        const float* wr = &ws[g * 256];
        for (int ic = 0; ic < 256; ++ic)
            acc = fmaf(xs[(ic << 5) + px], wr[ic], acc);
        const int s = s0 + px;
        if (g == 0)
            out_ctr[(size_t)n * HW + s] = acc;
        else
            out_reg[((size_t)n * 4 + (g - 1)) * HW + s] = fmaxf(acc * stride, 0.f);
    }
}

// ---------------------------------------------------------------------------
// Host launcher
// ---------------------------------------------------------------------------
extern "C" void kernel_launch(void* const* d_in, const int* in_sizes, int n_in,
                              void* d_out, int out_size) {
    (void)in_sizes; (void)n_in; (void)out_size;

    const float* fpn[5];
    for (int i = 0; i < 5; ++i) fpn[i] = (const float*)d_in[i];
    const float* cls_conv_w  = (const float*)d_in[5];
    const float* cls_scale   = (const float*)d_in[6];
    const float* cls_bias    = (const float*)d_in[7];
    const float* cls_final_w = (const float*)d_in[8];
    const float* cls_final_b = (const float*)d_in[9];
    const float* reg_conv_w  = (const float*)d_in[10];
    const float* reg_scale   = (const float*)d_in[11];
    const float* reg_bias    = (const float*)d_in[12];
    const float* reg_final_w = (const float*)d_in[13];
    const float* reg_final_b = (const float*)d_in[14];
    float* out = (float*)d_out;

    float *bufA, *bufB, *wfc;
    uint32_t* wb;
    cudaGetSymbolAddress((void**)&bufA, g_bufA);
    cudaGetSymbolAddress((void**)&bufB, g_bufB);
    cudaGetSymbolAddress((void**)&wb,   g_wb);
    cudaGetSymbolAddress((void**)&wfc,  g_wfc);

    cudaFuncSetAttribute(conv3x3_mma,
                         cudaFuncAttributeMaxDynamicSharedMemorySize,
                         SMEM_BYTES);

    const long HEADWORDS = 4L * 16 * 2 * 9 * 256 * 8;   // per head
    const long LAYERWORDS = HEADWORDS / 4;
    const long wtot = HEADWORDS;

    wsplit<<<(int)((wtot + 255) / 256), 256>>>(cls_conv_w, wb);
    wsplit<<<(int)((wtot + 255) / 256), 256>>>(reg_conv_w, wb + HEADWORDS);
    transpose_fc<<<(80 * 256 + 255) / 256, 256>>>(cls_final_w, wfc);

    const int Hs[5] = {128, 64, 32, 16, 8};
    const float strides[5] = {8.f, 16.f, 32.f, 64.f, 128.f};
    long HWs[5], clsOff[5], regOff[5], ctrOff[5];
    for (int l = 0; l < 5; ++l) HWs[l] = (long)Hs[l] * Hs[l];
    long off = 0;
    for (int l = 0; l < 5; ++l) { clsOff[l] = off; off += (long)NB * 80 * HWs[l]; }
    for (int l = 0; l < 5; ++l) { regOff[l] = off; off += (long)NB * 4 * HWs[l]; }
    for (int l = 0; l < 5; ++l) { ctrOff[l] = off; off += (long)NB * 1 * HWs[l]; }

    for (int l = 0; l < 5; ++l) {
        const int H = Hs[l], W = Hs[l];
        const int HW = H * W;
        const size_t headStride = (size_t)NB * ICH * HW;
        const int tX = (W + TX - 1) / TX;
        const int tY = (H + TY - 1) / TY;
        dim3 grid(tX * tY, OCH / 64, NB * 2);

        // 4 merged conv layers (both heads per launch)
        const float* s0 = fpn[l];
        const float* s1 = fpn[l];
        float* dst = nullptr;
        for (int i = 0; i < 4; ++i) {
            dst = (i & 1) ? bufB : bufA;
            conv3x3_mma<<<grid, 512, SMEM_BYTES>>>(
                s0, s1,
                wb + 0 * HEADWORDS + i * LAYERWORDS,
                wb + 1 * HEADWORDS + i * LAYERWORDS,
                cls_scale + i * ICH, reg_scale + i * ICH,
                cls_bias + i * ICH,  reg_bias + i * ICH,
                dst, headStride, H, W);
            s0 = dst;                 // head 0 region
            s1 = dst + headStride;    // head 1 region
        }

        const int fgrid = NB * HW / 32;
        final_conv_cls<<<fgrid, 256>>>(s0, wfc, cls_final_b,
                                       out + clsOff[l], HW);
        final_conv_reg<<<fgrid, 256>>>(s1, reg_final_w, reg_final_b,
                                       out + regOff[l], out + ctrOff[l],
                                       HW, strides[l]);
    }
}